// round 1
// baseline (speedup 1.0000x reference)
#include <cuda_runtime.h>
#include <math.h>

#define NN      100000      // nodes total
#define NATOMS  100
#define NGRAPH  1000
#define DEG     20
#define H       32
#define EDIM    51
#define NCONV   3
#define GDIM    16
#define TBL     16384       // he(d) table resolution

// ---- device scratch (static allocation is allowed) ----
__device__ float g_emb[NN * H];                 // atom embeddings (updated per layer)
__device__ float g_h[NN * H];                   // h = emb @ W_init^T per layer
__device__ float g_tbl[NCONV * TBL * H];        // he(d) tables, one per layer

__device__ __forceinline__ float tanh_fast(float x) {
    // accurate to ~1e-6 rel, stable for all x
    float e = __expf(-2.0f * fabsf(x));
    float t = (1.0f - e) / (1.0f + e);
    return copysignf(t, x);
}

// ============================================================
// Kernel 1: build he(d) tables.  grid = (TBL/8, NCONV), block = 256
// he_l(d) = tanh(rbf(d) @ Wf1_l^T + bf1_l) @ Wf2_l^T + bf2_l
// ============================================================
__global__ void build_table_kernel(const float* __restrict__ Wf1,
                                   const float* __restrict__ bf1,
                                   const float* __restrict__ Wf2,
                                   const float* __restrict__ bf2) {
    const int l = blockIdx.y;
    __shared__ float s_Wf1[H * EDIM];
    __shared__ float s_Wf2T[H * H];
    __shared__ float s_bf1[H], s_bf2[H];
    __shared__ float s_f1[8][H];

    int tid = threadIdx.x;
    for (int i = tid; i < H * EDIM; i += blockDim.x)
        s_Wf1[i] = Wf1[l * H * EDIM + i];
    for (int i = tid; i < H * H; i += blockDim.x) {
        int k = i / H, m = i % H;
        s_Wf2T[m * H + k] = Wf2[l * H * H + i];
    }
    if (tid < H) { s_bf1[tid] = bf1[l * H + tid]; s_bf2[tid] = bf2[l * H + tid]; }
    __syncthreads();

    int w = tid >> 5, k = tid & 31;
    int t = blockIdx.x * 8 + w;
    float d = (float)t * (10.0f / (float)(TBL - 1));

    float acc = s_bf1[k];
    for (int j = 0; j < EDIM; j++) {
        float dc = d - 0.2f * (float)j;
        float ee = expf(-dc * dc * 25.0f);       // exp(-(d-c)^2 / 0.2^2)
        acc = fmaf(ee, s_Wf1[k * EDIM + j], acc); // k*51+j: gcd(51,32)=1 -> conflict-free
    }
    float f1 = tanhf(acc);
    s_f1[w][k] = f1;
    __syncwarp();
    float he = s_bf2[k];
#pragma unroll
    for (int m = 0; m < H; m++)
        he = fmaf(s_f1[w][m], s_Wf2T[m * H + k], he);
    g_tbl[(l * TBL + t) * H + k] = he;
}

// ============================================================
// Kernel 2: init embeddings.  emb[n][k] = emb_table[n % 100][k]
// ============================================================
__global__ void init_emb_kernel(const float* __restrict__ emb_table) {
    int idx = blockIdx.x * blockDim.x + threadIdx.x;
    if (idx < NN * H) {
        int n = idx >> 5, k = idx & 31;
        g_emb[idx] = emb_table[(n % NATOMS) * H + k];
    }
}

// ============================================================
// Kernel 3: h = emb @ W_init[l]^T.  warp per node, lane = out feature.
// ============================================================
__global__ void compute_h_kernel(const float* __restrict__ W_init, int layer) {
    __shared__ float s_WT[H * H];       // [m][k] = W_init[l][k][m]
    __shared__ float s_row[8][H];
    int tid = threadIdx.x;
    for (int i = tid; i < H * H; i += blockDim.x) {
        int k = i / H, m = i % H;
        s_WT[m * H + k] = W_init[layer * H * H + i];
    }
    __syncthreads();
    int w = tid >> 5, lane = tid & 31;
    int node = blockIdx.x * 8 + w;
    s_row[w][lane] = g_emb[node * H + lane];
    __syncwarp();
    float h = 0.f;
#pragma unroll
    for (int m = 0; m < H; m++)
        h = fmaf(s_row[w][m], s_WT[m * H + lane], h);
    g_h[node * H + lane] = h;
}

// ============================================================
// Kernel 4: message passing + attention + output MLP + residual.
// warp per node (edges of node n are rows [n*20, n*20+20) -- src is
// repeat(arange(NN), DEG) by construction, so no atomics needed).
// ============================================================
__global__ void conv_kernel(const float* __restrict__ data,
                            const float* __restrict__ coef,
                            const float* __restrict__ Wo1, const float* __restrict__ bo1,
                            const float* __restrict__ Wo2, const float* __restrict__ bo2,
                            int layer) {
    __shared__ float s_Wo1T[H * H], s_Wo2T[H * H];   // transposed [m][k]
    __shared__ float s_bo1[H], s_bo2[H], s_coef[H];
    __shared__ float s_edge[8][64];                  // 60 floats of edge data per node
    __shared__ float s_vec[8][H];

    int tid = threadIdx.x;
    for (int i = tid; i < H * H; i += blockDim.x) {
        int k = i / H, m = i % H;
        s_Wo1T[m * H + k] = Wo1[layer * H * H + i];
        s_Wo2T[m * H + k] = Wo2[layer * H * H + i];
    }
    if (tid < H) {
        s_bo1[tid]  = bo1[layer * H + tid];
        s_bo2[tid]  = bo2[layer * H + tid];
        s_coef[tid] = coef[layer * H + tid];
    }
    __syncthreads();

    int w = tid >> 5, lane = tid & 31;
    int node = blockIdx.x * 8 + w;

    // load this node's 20 edges (60 contiguous floats), coalesced
    const float* ed = data + (size_t)node * (DEG * 3);
    s_edge[w][lane] = ed[lane];
    if (lane < DEG * 3 - 32) s_edge[w][32 + lane] = ed[32 + lane];
    __syncwarp();

    const float* __restrict__ tbl = g_tbl + layer * TBL * H;
    const float cscale = (float)(TBL - 1) * 0.1f;   // (TBL-1)/10

    float numer = 0.f, denom = 0.f;
#pragma unroll 4
    for (int e = 0; e < DEG; e++) {
        float dstf = s_edge[w][e * 3 + 1];
        float dist = s_edge[w][e * 3 + 2];
        int dst = (int)dstf;

        float hd = __ldg(&g_h[dst * H + lane]);

        float u = fmaxf(dist * cscale, 0.f);
        int i0 = (int)u;
        i0 = min(i0, TBL - 2);
        float fr = u - (float)i0;
        const float* tp = tbl + i0 * H + lane;
        float t0 = __ldg(tp), t1 = __ldg(tp + H);
        float he = fmaf(fr, t1 - t0, t0);

        float msg = hd * he;
        float s = msg * s_coef[lane];
#pragma unroll
        for (int off = 16; off; off >>= 1)
            s += __shfl_xor_sync(0xffffffffu, s, off);
        float a = __expf(s);
        numer = fmaf(msg, a, numer);
        denom += a;
    }

    float conv = (denom > 0.f) ? (numer / denom) : numer;

    s_vec[w][lane] = conv;
    __syncwarp();
    float o1 = s_bo1[lane];
#pragma unroll
    for (int m = 0; m < H; m++)
        o1 = fmaf(s_vec[w][m], s_Wo1T[m * H + lane], o1);
    o1 = tanh_fast(o1);
    __syncwarp();
    s_vec[w][lane] = o1;
    __syncwarp();
    float o2 = s_bo2[lane];
#pragma unroll
    for (int m = 0; m < H; m++)
        o2 = fmaf(s_vec[w][m], s_Wo2T[m * H + lane], o2);

    g_emb[node * H + lane] += o2;
}

// ============================================================
// Kernel 5: per-graph pooling + final linear.  block per graph.
// ============================================================
__global__ void pool_kernel(const float* __restrict__ Wg,
                            const float* __restrict__ bg,
                            float* __restrict__ out) {
    __shared__ float s_acc[4][H];
    __shared__ float s_p[H];
    int g = blockIdx.x;
    int tid = threadIdx.x;
    int w = tid >> 5, lane = tid & 31;

    float acc = 0.f;
    for (int a = w; a < NATOMS; a += 4)
        acc += fmaxf(g_emb[(g * NATOMS + a) * H + lane], 0.f);
    s_acc[w][lane] = acc;
    __syncthreads();

    if (w == 0) {
        float p = (s_acc[0][lane] + s_acc[1][lane] + s_acc[2][lane] + s_acc[3][lane])
                  * (1.0f / (float)NATOMS);
        s_p[lane] = p;
        __syncwarp();
        if (lane < GDIM) {
            float o = bg[lane];
#pragma unroll
            for (int k = 0; k < H; k++)
                o = fmaf(s_p[k], Wg[lane * H + k], o);
            out[g * GDIM + lane] = o;
        }
    }
}

// ============================================================
extern "C" void kernel_launch(void* const* d_in, const int* in_sizes, int n_in,
                              void* d_out, int out_size) {
    const float* data      = (const float*)d_in[0];
    const float* emb_table = (const float*)d_in[1];
    const float* W_init    = (const float*)d_in[2];
    const float* Wf1       = (const float*)d_in[3];
    const float* bf1       = (const float*)d_in[4];
    const float* Wf2       = (const float*)d_in[5];
    const float* bf2       = (const float*)d_in[6];
    const float* coef      = (const float*)d_in[7];
    const float* Wo1       = (const float*)d_in[8];
    const float* bo1       = (const float*)d_in[9];
    const float* Wo2       = (const float*)d_in[10];
    const float* bo2       = (const float*)d_in[11];
    const float* Wg        = (const float*)d_in[12];
    const float* bg        = (const float*)d_in[13];
    float* out = (float*)d_out;

    build_table_kernel<<<dim3(TBL / 8, NCONV), 256>>>(Wf1, bf1, Wf2, bf2);
    init_emb_kernel<<<(NN * H + 255) / 256, 256>>>(emb_table);
    for (int l = 0; l < NCONV; l++) {
        compute_h_kernel<<<NN / 8, 256>>>(W_init, l);
        conv_kernel<<<NN / 8, 256>>>(data, coef, Wo1, bo1, Wo2, bo2, l);
    }
    pool_kernel<<<NGRAPH, 128>>>(Wg, bg, out);
}

// round 2
// speedup vs baseline: 1.4884x; 1.4884x over previous
#include <cuda_runtime.h>
#include <math.h>

#define NN      100000
#define NATOMS  100
#define NGRAPH  1000
#define DEG     20
#define H       32
#define EDIM    51
#define NCONV   3
#define GDIM    16
#define TBL     32768       // he(d) table intervals; (value, slope) per entry

// ---- device scratch ----
__device__ float  g_emb[NN * H];                    // embeddings between layers
__device__ float  g_raw[NCONV * (TBL + 1) * H];     // he at grid points
__device__ float2 g_tblp[NCONV * TBL * H];          // (value, slope) per interval

__device__ __forceinline__ float tanh_fast(float x) {
    float e = __expf(-2.0f * fabsf(x));
    float t = (1.0f - e) / (1.0f + e);
    return copysignf(t, x);
}

// ============================================================
// Table build: he_l(d) = tanh(rbf(d)@Wf1^T + bf1)@Wf2^T + bf2
// at TBL+1 grid points.  RBF exps computed once per row (cooperative).
// grid = (ceil((TBL+1)/8), NCONV), block = 256
// ============================================================
__global__ void build_raw_kernel(const float* __restrict__ Wf1,
                                 const float* __restrict__ bf1,
                                 const float* __restrict__ Wf2,
                                 const float* __restrict__ bf2) {
    const int l = blockIdx.y;
    __shared__ float s_Wf1[H * EDIM];
    __shared__ float s_Wf2T[H * H];
    __shared__ float s_bf1[H], s_bf2[H];
    __shared__ float s_ee[8][EDIM];
    __shared__ float s_f1[8][H];

    int tid = threadIdx.x;
    for (int i = tid; i < H * EDIM; i += blockDim.x)
        s_Wf1[i] = Wf1[l * H * EDIM + i];
    for (int i = tid; i < H * H; i += blockDim.x) {
        int k = i / H, m = i % H;
        s_Wf2T[m * H + k] = Wf2[l * H * H + i];
    }
    if (tid < H) { s_bf1[tid] = bf1[l * H + tid]; s_bf2[tid] = bf2[l * H + tid]; }
    __syncthreads();

    int w = tid >> 5, lane = tid & 31;
    int t = blockIdx.x * 8 + w;
    if (t > TBL) return;
    float d = (float)t * (10.0f / (float)TBL);

    // cooperative RBF: lane j computes ee_j (j and j+32)
    for (int j = lane; j < EDIM; j += 32) {
        float dc = d - 0.2f * (float)j;
        s_ee[w][j] = __expf(-25.0f * dc * dc);
    }
    __syncwarp();

    float acc = s_bf1[lane];
    for (int j = 0; j < EDIM; j++)
        acc = fmaf(s_ee[w][j], s_Wf1[lane * EDIM + j], acc);  // stride 51: conflict-free
    s_f1[w][lane] = tanh_fast(acc);
    __syncwarp();

    float he = s_bf2[lane];
#pragma unroll
    for (int m = 0; m < H; m++)
        he = fmaf(s_f1[w][m], s_Wf2T[m * H + lane], he);
    g_raw[(l * (TBL + 1) + t) * H + lane] = he;
}

// pack (value, slope) pairs
__global__ void pack_table_kernel() {
    int idx = blockIdx.x * blockDim.x + threadIdx.x;
    if (idx >= NCONV * TBL * H) return;
    int l = idx / (TBL * H);
    int r = idx - l * (TBL * H);
    int i = r >> 5, k = r & 31;
    float v0 = g_raw[(l * (TBL + 1) + i) * H + k];
    float v1 = g_raw[(l * (TBL + 1) + i + 1) * H + k];
    g_tblp[idx] = make_float2(v0, v1 - v0);
}

// ============================================================
// Fused layer kernel: block per graph.
//   Phase A: h = emb @ W_init^T for all 100 atoms -> smem
//   Phase B: per node: 20 edges (smem h gather + table LDG),
//            attention, output MLP, residual.
//   layer 0 reads emb_table directly; layer 2 fuses relu-pool+linear.
// ============================================================
__global__ void __launch_bounds__(256)
layer_kernel(const float* __restrict__ data,
             const float* __restrict__ emb_table,
             const float* __restrict__ W_init,
             const float* __restrict__ coef,
             const float* __restrict__ Wo1, const float* __restrict__ bo1,
             const float* __restrict__ Wo2, const float* __restrict__ bo2,
             const float* __restrict__ Wg,  const float* __restrict__ bg,
             float* __restrict__ out, int layer) {
    __shared__ float s_h[NATOMS * H];        // 12.8 KB
    __shared__ float s_WiT[H * H];
    __shared__ float s_Wo1T[H * H], s_Wo2T[H * H];
    __shared__ float s_bo1[H], s_bo2[H], s_coef[H];
    __shared__ float s_edge[8][64];          // per-warp scratch (edges / vectors)
    __shared__ float s_WgT[H * GDIM];        // last layer only
    __shared__ float s_pooled[H];

    const int tid  = threadIdx.x;
    const int w    = tid >> 5;
    const int lane = tid & 31;
    const int g    = blockIdx.x;
    const int base = g * NATOMS;

    for (int i = tid; i < H * H; i += 256) {
        int k = i >> 5, m = i & 31;
        s_WiT [m * H + k] = W_init[layer * H * H + i];
        s_Wo1T[m * H + k] = Wo1[layer * H * H + i];
        s_Wo2T[m * H + k] = Wo2[layer * H * H + i];
    }
    if (tid < H) {
        s_bo1[tid]  = bo1[layer * H + tid];
        s_bo2[tid]  = bo2[layer * H + tid];
        s_coef[tid] = coef[layer * H + tid];
    }
    if (layer == NCONV - 1) {
        for (int i = tid; i < GDIM * H; i += 256) {
            int j = i >> 5, k = i & 31;          // Wg[j][k]
            s_WgT[k * GDIM + j] = Wg[i];
        }
    }
    __syncthreads();

    // ---------- Phase A: h for the whole graph ----------
    for (int a = w; a < NATOMS; a += 8) {
        float e = (layer == 0) ? emb_table[a * H + lane]
                               : g_emb[(base + a) * H + lane];
        s_edge[w][lane] = e;
        __syncwarp();
        float h = 0.f;
#pragma unroll
        for (int m = 0; m < H; m++)
            h = fmaf(s_edge[w][m], s_WiT[m * H + lane], h);
        s_h[a * H + lane] = h;
        __syncwarp();
    }
    __syncthreads();

    // ---------- Phase B: conv per node ----------
    const float2* __restrict__ tbl = g_tblp + (size_t)layer * TBL * H;
    const float uscale = (float)TBL * 0.1f;
    float poolacc = 0.f;

    for (int a = w; a < NATOMS; a += 8) {
        const int node = base + a;
        const float* ed = data + (size_t)node * (DEG * 3);
        s_edge[w][lane] = ed[lane];
        if (lane < DEG * 3 - 32) s_edge[w][32 + lane] = ed[32 + lane];
        __syncwarp();

        float numer = 0.f, denom = 0.f;
#pragma unroll 2
        for (int e = 0; e < DEG; e += 2) {
            // edge A
            int   dA  = (int)s_edge[w][e * 3 + 1] - base;
            float uA  = s_edge[w][e * 3 + 2] * uscale;
            int   iA  = min((int)uA, TBL - 1);
            float frA = uA - (float)iA;
            float hdA = s_h[dA * H + lane];
            float2 pA = __ldg(&tbl[(iA << 5) + lane]);
            float msgA = hdA * fmaf(frA, pA.y, pA.x);
            // edge B
            int   dB  = (int)s_edge[w][e * 3 + 4] - base;
            float uB  = s_edge[w][e * 3 + 5] * uscale;
            int   iB  = min((int)uB, TBL - 1);
            float frB = uB - (float)iB;
            float hdB = s_h[dB * H + lane];
            float2 pB = __ldg(&tbl[(iB << 5) + lane]);
            float msgB = hdB * fmaf(frB, pB.y, pB.x);

            // paired 2-edge reduction: 8 shfl for 2 dot products
            float qA = msgA * s_coef[lane];
            float qB = msgB * s_coef[lane];
            float tA = qA + __shfl_xor_sync(0xffffffffu, qA, 16);
            float tB = qB + __shfl_xor_sync(0xffffffffu, qB, 16);
            float u0 = (lane & 16) ? tB : tA;
            u0 += __shfl_xor_sync(0xffffffffu, u0, 8);
            u0 += __shfl_xor_sync(0xffffffffu, u0, 4);
            u0 += __shfl_xor_sync(0xffffffffu, u0, 2);
            u0 += __shfl_xor_sync(0xffffffffu, u0, 1);
            float sA = __shfl_sync(0xffffffffu, u0, 0);
            float sB = __shfl_sync(0xffffffffu, u0, 16);

            float aA = __expf(sA), aB = __expf(sB);
            numer = fmaf(msgA, aA, numer);
            numer = fmaf(msgB, aB, numer);
            denom += aA + aB;
        }

        float conv = (denom > 0.f) ? (numer / denom) : numer;

        // output MLP (reuse s_edge row as staging)
        __syncwarp();
        s_edge[w][lane] = conv;
        __syncwarp();
        float o1 = s_bo1[lane];
#pragma unroll
        for (int m = 0; m < H; m++)
            o1 = fmaf(s_edge[w][m], s_Wo1T[m * H + lane], o1);
        o1 = tanh_fast(o1);
        s_edge[w][32 + lane] = o1;
        __syncwarp();
        float o2 = s_bo2[lane];
#pragma unroll
        for (int m = 0; m < H; m++)
            o2 = fmaf(s_edge[w][32 + m], s_Wo2T[m * H + lane], o2);

        float old = (layer == 0) ? emb_table[a * H + lane]
                                 : g_emb[node * H + lane];
        float ne = old + o2;
        if (layer < NCONV - 1) g_emb[node * H + lane] = ne;
        else                   poolacc += fmaxf(ne, 0.f);
        __syncwarp();
    }

    // ---------- last layer: fused pool + final linear ----------
    if (layer == NCONV - 1) {
        s_edge[w][lane] = poolacc;       // warp-private row, loop done
        __syncthreads();
        if (w == 0) {
            float p = 0.f;
#pragma unroll
            for (int i = 0; i < 8; i++) p += s_edge[i][lane];
            s_pooled[lane] = p * (1.0f / (float)NATOMS);
            __syncwarp();
            if (lane < GDIM) {
                float o = bg[lane];
#pragma unroll
                for (int k = 0; k < H; k++)
                    o = fmaf(s_pooled[k], s_WgT[k * GDIM + lane], o);
                out[g * GDIM + lane] = o;
            }
        }
    }
}

// ============================================================
extern "C" void kernel_launch(void* const* d_in, const int* in_sizes, int n_in,
                              void* d_out, int out_size) {
    const float* data      = (const float*)d_in[0];
    const float* emb_table = (const float*)d_in[1];
    const float* W_init    = (const float*)d_in[2];
    const float* Wf1       = (const float*)d_in[3];
    const float* bf1       = (const float*)d_in[4];
    const float* Wf2       = (const float*)d_in[5];
    const float* bf2       = (const float*)d_in[6];
    const float* coef      = (const float*)d_in[7];
    const float* Wo1       = (const float*)d_in[8];
    const float* bo1       = (const float*)d_in[9];
    const float* Wo2       = (const float*)d_in[10];
    const float* bo2       = (const float*)d_in[11];
    const float* Wg        = (const float*)d_in[12];
    const float* bg        = (const float*)d_in[13];
    float* out = (float*)d_out;

    build_raw_kernel<<<dim3((TBL + 1 + 7) / 8, NCONV), 256>>>(Wf1, bf1, Wf2, bf2);
    pack_table_kernel<<<(NCONV * TBL * H + 255) / 256, 256>>>();
    for (int l = 0; l < NCONV; l++)
        layer_kernel<<<NGRAPH, 256>>>(data, emb_table, W_init, coef,
                                      Wo1, bo1, Wo2, bo2, Wg, bg, out, l);
}

// round 4
// speedup vs baseline: 1.9914x; 1.3379x over previous
#include <cuda_runtime.h>
#include <math.h>

#define NN      100000
#define NATOMS  100
#define NGRAPH  1000
#define DEG     20
#define H       32
#define EDIM    51
#define NCONV   3
#define GDIM    16
#define TBL     4096        // he(d) table intervals; (value, slope) per entry

// ---- device scratch ----
__device__ float    g_raw[NCONV * (TBL + 1) * H];   // he at grid points
__device__ float2   g_tblp[NCONV * TBL * H];        // (value, slope) per interval
__device__ unsigned g_edges[NN * DEG];              // packed (dst_local|i0|fr13)

__device__ __forceinline__ float tanh_fast(float x) {
    float e = __expf(-2.0f * fabsf(x));
    float t = (1.0f - e) / (1.0f + e);
    return copysignf(t, x);
}

// ============================================================
// Table build: he_l(d) at TBL+1 grid points.
// ============================================================
__global__ void build_raw_kernel(const float* __restrict__ Wf1,
                                 const float* __restrict__ bf1,
                                 const float* __restrict__ Wf2,
                                 const float* __restrict__ bf2) {
    const int l = blockIdx.y;
    __shared__ float s_Wf1[H * EDIM];
    __shared__ float s_Wf2T[H * H];
    __shared__ float s_bf1[H], s_bf2[H];
    __shared__ float s_ee[8][EDIM];
    __shared__ float s_f1[8][H];

    int tid = threadIdx.x;
    for (int i = tid; i < H * EDIM; i += blockDim.x)
        s_Wf1[i] = Wf1[l * H * EDIM + i];
    for (int i = tid; i < H * H; i += blockDim.x) {
        int k = i / H, m = i % H;
        s_Wf2T[m * H + k] = Wf2[l * H * H + i];
    }
    if (tid < H) { s_bf1[tid] = bf1[l * H + tid]; s_bf2[tid] = bf2[l * H + tid]; }
    __syncthreads();

    int w = tid >> 5, lane = tid & 31;
    int t = blockIdx.x * 8 + w;
    if (t > TBL) return;
    float d = (float)t * (10.0f / (float)TBL);

    for (int j = lane; j < EDIM; j += 32) {
        float dc = d - 0.2f * (float)j;
        s_ee[w][j] = __expf(-25.0f * dc * dc);
    }
    __syncwarp();

    float acc = s_bf1[lane];
    for (int j = 0; j < EDIM; j++)
        acc = fmaf(s_ee[w][j], s_Wf1[lane * EDIM + j], acc);
    s_f1[w][lane] = tanh_fast(acc);
    __syncwarp();

    float he = s_bf2[lane];
#pragma unroll
    for (int m = 0; m < H; m++)
        he = fmaf(s_f1[w][m], s_Wf2T[m * H + lane], he);
    g_raw[(l * (TBL + 1) + t) * H + lane] = he;
}

__global__ void pack_table_kernel() {
    int idx = blockIdx.x * blockDim.x + threadIdx.x;
    if (idx >= NCONV * TBL * H) return;
    int l = idx / (TBL * H);
    int r = idx - l * (TBL * H);
    int i = r >> 5, k = r & 31;
    float v0 = g_raw[(l * (TBL + 1) + i) * H + k];
    float v1 = g_raw[(l * (TBL + 1) + i + 1) * H + k];
    g_tblp[idx] = make_float2(v0, v1 - v0);
}

// ============================================================
// Edge pre-pack: one uint32 per edge:
//   bits [0:7)   dst_local   (< 100)
//   bits [7:19)  i0          (< 4096)
//   bits [19:32) fr * 8192   (13 bits)
// ============================================================
__global__ void pack_edges_kernel(const float* __restrict__ data) {
    int e = blockIdx.x * blockDim.x + threadIdx.x;
    if (e >= NN * DEG) return;
    int src   = e / DEG;
    int base  = (src / NATOMS) * NATOMS;
    int dl    = (int)data[e * 3 + 1] - base;
    float u   = data[e * 3 + 2] * ((float)TBL * 0.1f);
    int i0    = min((int)u, TBL - 1);
    int fri   = min((int)((u - (float)i0) * 8192.0f), 8191);
    g_edges[e] = (unsigned)dl | ((unsigned)i0 << 7) | ((unsigned)fri << 19);
}

// ============================================================
// Fused 3-layer kernel: block per graph, emb resident in smem.
// ============================================================
__global__ void __launch_bounds__(256)
fused_kernel(const float* __restrict__ emb_table,
             const float* __restrict__ W_init,
             const float* __restrict__ coef,
             const float* __restrict__ Wo1, const float* __restrict__ bo1,
             const float* __restrict__ Wo2, const float* __restrict__ bo2,
             const float* __restrict__ Wg,  const float* __restrict__ bg,
             float* __restrict__ out) {
    __shared__ float s_emb[NATOMS * H];      // 12.8 KB, persists across layers
    __shared__ float s_h[NATOMS * H];        // 12.8 KB
    __shared__ float s_WiT[H * H];
    __shared__ float s_Wo1T[H * H], s_Wo2T[H * H];
    __shared__ float s_bo1[H], s_bo2[H], s_coef[H];
    __shared__ float s_vec[8][H];            // per-warp staging
    __shared__ float s_WgT[H * GDIM];
    __shared__ float s_pooled[H];

    const int tid  = threadIdx.x;
    const int w    = tid >> 5;
    const int lane = tid & 31;
    const int g    = blockIdx.x;
    const int base = g * NATOMS;

    for (int i = tid; i < GDIM * H; i += 256) {
        int j = i >> 5, k = i & 31;
        s_WgT[k * GDIM + j] = Wg[i];
    }

    float poolacc = 0.f;

    for (int l = 0; l < NCONV; l++) {
        // ---- weights for this layer ----
        for (int i = tid; i < H * H; i += 256) {
            int k = i >> 5, m = i & 31;
            s_WiT [m * H + k] = W_init[l * H * H + i];
            s_Wo1T[m * H + k] = Wo1[l * H * H + i];
            s_Wo2T[m * H + k] = Wo2[l * H * H + i];
        }
        if (tid < H) {
            s_bo1[tid]  = bo1[l * H + tid];
            s_bo2[tid]  = bo2[l * H + tid];
            s_coef[tid] = coef[l * H + tid];
        }
        __syncthreads();

        // ---- Phase A: h = emb @ W_init^T for whole graph ----
        for (int a = w; a < NATOMS; a += 8) {
            float e;
            if (l == 0) {
                e = emb_table[a * H + lane];
                s_emb[a * H + lane] = e;
            } else {
                e = s_emb[a * H + lane];
            }
            s_vec[w][lane] = e;
            __syncwarp();
            float h = 0.f;
#pragma unroll
            for (int m = 0; m < H; m++)
                h = fmaf(s_vec[w][m], s_WiT[m * H + lane], h);
            s_h[a * H + lane] = h;
            __syncwarp();
        }
        __syncthreads();

        // ---- Phase B: conv + MLP + residual per node ----
        const float2* __restrict__ tbl = g_tblp + (size_t)l * TBL * H;
        const float cf = s_coef[lane];

        for (int a = w; a < NATOMS; a += 8) {
            const int node = base + a;
            unsigned pk = 0;
            if (lane < DEG) pk = g_edges[node * DEG + lane];

            float numer = 0.f, denom = 0.f;
#pragma unroll
            for (int e = 0; e < DEG; e += 4) {
                unsigned p0 = __shfl_sync(0xffffffffu, pk, e + 0);
                unsigned p1 = __shfl_sync(0xffffffffu, pk, e + 1);
                unsigned p2 = __shfl_sync(0xffffffffu, pk, e + 2);
                unsigned p3 = __shfl_sync(0xffffffffu, pk, e + 3);

                float2 tb0 = __ldg(&tbl[(((p0 >> 7) & 4095) << 5) + lane]);
                float2 tb1 = __ldg(&tbl[(((p1 >> 7) & 4095) << 5) + lane]);
                float2 tb2 = __ldg(&tbl[(((p2 >> 7) & 4095) << 5) + lane]);
                float2 tb3 = __ldg(&tbl[(((p3 >> 7) & 4095) << 5) + lane]);

                float hd0 = s_h[((p0 & 127u) << 5) + lane];
                float hd1 = s_h[((p1 & 127u) << 5) + lane];
                float hd2 = s_h[((p2 & 127u) << 5) + lane];
                float hd3 = s_h[((p3 & 127u) << 5) + lane];

                const float fq = 1.0f / 8192.0f;
                float m0 = hd0 * fmaf((float)(p0 >> 19) * fq, tb0.y, tb0.x);
                float m1 = hd1 * fmaf((float)(p1 >> 19) * fq, tb1.y, tb1.x);
                float m2 = hd2 * fmaf((float)(p2 >> 19) * fq, tb2.y, tb2.x);
                float m3 = hd3 * fmaf((float)(p3 >> 19) * fq, tb3.y, tb3.x);

                // 4-score batched reduction.
                // Fold each score with xor16 AND xor8 so every 8-lane quad
                // holds a partition of the full 32-lane sum; then reduce
                // within the quad only (xor 4,2,1).
                float q0 = m0 * cf, q1 = m1 * cf, q2 = m2 * cf, q3 = m3 * cf;
                float t0 = q0 + __shfl_xor_sync(0xffffffffu, q0, 16);
                float t1 = q1 + __shfl_xor_sync(0xffffffffu, q1, 16);
                float t2 = q2 + __shfl_xor_sync(0xffffffffu, q2, 16);
                float t3 = q3 + __shfl_xor_sync(0xffffffffu, q3, 16);
                t0 += __shfl_xor_sync(0xffffffffu, t0, 8);
                t1 += __shfl_xor_sync(0xffffffffu, t1, 8);
                t2 += __shfl_xor_sync(0xffffffffu, t2, 8);
                t3 += __shfl_xor_sync(0xffffffffu, t3, 8);
                int quad = lane >> 3;
                float u = (quad == 0) ? t0 : (quad == 1) ? t1 : (quad == 2) ? t2 : t3;
                u += __shfl_xor_sync(0xffffffffu, u, 4);
                u += __shfl_xor_sync(0xffffffffu, u, 2);
                u += __shfl_xor_sync(0xffffffffu, u, 1);
                float av = __expf(u);                 // one expf per 4 edges
                float a0 = __shfl_sync(0xffffffffu, av, 0);
                float a1 = __shfl_sync(0xffffffffu, av, 8);
                float a2 = __shfl_sync(0xffffffffu, av, 16);
                float a3 = __shfl_sync(0xffffffffu, av, 24);

                numer = fmaf(m0, a0, numer);
                numer = fmaf(m1, a1, numer);
                numer = fmaf(m2, a2, numer);
                numer = fmaf(m3, a3, numer);
                denom += (a0 + a1) + (a2 + a3);
            }

            float conv = (denom > 0.f) ? (numer / denom) : numer;

            // output MLP
            s_vec[w][lane] = conv;
            __syncwarp();
            float o1 = s_bo1[lane];
#pragma unroll
            for (int m = 0; m < H; m++)
                o1 = fmaf(s_vec[w][m], s_Wo1T[m * H + lane], o1);
            o1 = tanh_fast(o1);
            __syncwarp();
            s_vec[w][lane] = o1;
            __syncwarp();
            float o2 = s_bo2[lane];
#pragma unroll
            for (int m = 0; m < H; m++)
                o2 = fmaf(s_vec[w][m], s_Wo2T[m * H + lane], o2);

            float ne = s_emb[a * H + lane] + o2;
            if (l < NCONV - 1) s_emb[a * H + lane] = ne;
            else               poolacc += fmaxf(ne, 0.f);
            __syncwarp();
        }
        __syncthreads();
    }

    // ---- fused pool + final linear ----
    s_vec[w][lane] = poolacc;
    __syncthreads();
    if (w == 0) {
        float p = 0.f;
#pragma unroll
        for (int i = 0; i < 8; i++) p += s_vec[i][lane];
        s_pooled[lane] = p * (1.0f / (float)NATOMS);
        __syncwarp();
        if (lane < GDIM) {
            float o = bg[lane];
#pragma unroll
            for (int k = 0; k < H; k++)
                o = fmaf(s_pooled[k], s_WgT[k * GDIM + lane], o);
            out[g * GDIM + lane] = o;
        }
    }
}

// ============================================================
extern "C" void kernel_launch(void* const* d_in, const int* in_sizes, int n_in,
                              void* d_out, int out_size) {
    const float* data      = (const float*)d_in[0];
    const float* emb_table = (const float*)d_in[1];
    const float* W_init    = (const float*)d_in[2];
    const float* Wf1       = (const float*)d_in[3];
    const float* bf1       = (const float*)d_in[4];
    const float* Wf2       = (const float*)d_in[5];
    const float* bf2       = (const float*)d_in[6];
    const float* coef      = (const float*)d_in[7];
    const float* Wo1       = (const float*)d_in[8];
    const float* bo1       = (const float*)d_in[9];
    const float* Wo2       = (const float*)d_in[10];
    const float* bo2       = (const float*)d_in[11];
    const float* Wg        = (const float*)d_in[12];
    const float* bg        = (const float*)d_in[13];
    float* out = (float*)d_out;

    build_raw_kernel<<<dim3((TBL + 1 + 7) / 8, NCONV), 256>>>(Wf1, bf1, Wf2, bf2);
    pack_edges_kernel<<<(NN * DEG + 255) / 256, 256>>>(data);
    pack_table_kernel<<<(NCONV * TBL * H + 255) / 256, 256>>>();
    fused_kernel<<<NGRAPH, 256>>>(emb_table, W_init, coef,
                                  Wo1, bo1, Wo2, bo2, Wg, bg, out);
}

// round 5
// speedup vs baseline: 2.3553x; 1.1827x over previous
#include <cuda_runtime.h>
#include <math.h>

#define NN      100000
#define NATOMS  100
#define NGRAPH  1000
#define DEG     20
#define H       32
#define EDIM    51
#define NCONV   3
#define GDIM    16
#define TBL     4096        // he(d) table intervals; (value, slope) per entry

// ---- device scratch ----
__device__ float    g_raw[NCONV * (TBL + 1) * H];   // he at grid points
__device__ float2   g_tblp[NCONV * TBL * H];        // (value, slope) per interval
__device__ unsigned g_edges[NN * DEG];              // packed (dst_local|i0|fr13)

__device__ __forceinline__ float tanh_fast(float x) {
    float e = __expf(-2.0f * fabsf(x));
    float t = (1.0f - e) / (1.0f + e);
    return copysignf(t, x);
}

// ============================================================
// Table build: he_l(d) at TBL+1 grid points.
// ============================================================
__global__ void build_raw_kernel(const float* __restrict__ Wf1,
                                 const float* __restrict__ bf1,
                                 const float* __restrict__ Wf2,
                                 const float* __restrict__ bf2) {
    const int l = blockIdx.y;
    __shared__ float s_Wf1[H * EDIM];
    __shared__ float s_Wf2T[H * H];
    __shared__ float s_bf1[H], s_bf2[H];
    __shared__ float s_ee[8][EDIM];
    __shared__ float s_f1[8][H];

    int tid = threadIdx.x;
    for (int i = tid; i < H * EDIM; i += blockDim.x)
        s_Wf1[i] = Wf1[l * H * EDIM + i];
    for (int i = tid; i < H * H; i += blockDim.x) {
        int k = i / H, m = i % H;
        s_Wf2T[m * H + k] = Wf2[l * H * H + i];
    }
    if (tid < H) { s_bf1[tid] = bf1[l * H + tid]; s_bf2[tid] = bf2[l * H + tid]; }
    __syncthreads();

    int w = tid >> 5, lane = tid & 31;
    int t = blockIdx.x * 8 + w;
    if (t > TBL) return;
    float d = (float)t * (10.0f / (float)TBL);

    for (int j = lane; j < EDIM; j += 32) {
        float dc = d - 0.2f * (float)j;
        s_ee[w][j] = __expf(-25.0f * dc * dc);
    }
    __syncwarp();

    float acc = s_bf1[lane];
    for (int j = 0; j < EDIM; j++)
        acc = fmaf(s_ee[w][j], s_Wf1[lane * EDIM + j], acc);
    s_f1[w][lane] = tanh_fast(acc);
    __syncwarp();

    float he = s_bf2[lane];
#pragma unroll
    for (int m = 0; m < H; m++)
        he = fmaf(s_f1[w][m], s_Wf2T[m * H + lane], he);
    g_raw[(l * (TBL + 1) + t) * H + lane] = he;
}

__global__ void pack_table_kernel() {
    int idx = blockIdx.x * blockDim.x + threadIdx.x;
    if (idx >= NCONV * TBL * H) return;
    int l = idx / (TBL * H);
    int r = idx - l * (TBL * H);
    int i = r >> 5, k = r & 31;
    float v0 = g_raw[(l * (TBL + 1) + i) * H + k];
    float v1 = g_raw[(l * (TBL + 1) + i + 1) * H + k];
    g_tblp[idx] = make_float2(v0, v1 - v0);
}

// ============================================================
// Edge pre-pack: bits [0:7) dst_local, [7:19) i0, [19:32) fr*8192
// ============================================================
__global__ void pack_edges_kernel(const float* __restrict__ data) {
    int e = blockIdx.x * blockDim.x + threadIdx.x;
    if (e >= NN * DEG) return;
    int src   = e / DEG;
    int base  = (src / NATOMS) * NATOMS;
    int dl    = (int)data[e * 3 + 1] - base;
    float u   = data[e * 3 + 2] * ((float)TBL * 0.1f);
    int i0    = min((int)u, TBL - 1);
    int fri   = min((int)((u - (float)i0) * 8192.0f), 8191);
    g_edges[e] = (unsigned)dl | ((unsigned)i0 << 7) | ((unsigned)fri << 19);
}

// ============================================================
// Fused 3-layer kernel: block per graph.
// 16 lanes per node, 2 features per lane -> 2 nodes per warp.
// ============================================================
__global__ void __launch_bounds__(256, 5)
fused_kernel(const float* __restrict__ emb_table,
             const float* __restrict__ W_init,
             const float* __restrict__ coef,
             const float* __restrict__ Wo1, const float* __restrict__ bo1,
             const float* __restrict__ Wo2, const float* __restrict__ bo2,
             const float* __restrict__ Wg,  const float* __restrict__ bg,
             float* __restrict__ out) {
    __shared__ float s_emb[NATOMS * H];      // 12.8 KB
    __shared__ float s_h[NATOMS * H];        // 12.8 KB
    __shared__ float s_WiT[H * H];
    __shared__ float s_Wo1T[H * H], s_Wo2T[H * H];
    __shared__ float s_bo1[H], s_bo2[H], s_coef[H];
    __shared__ float s_warp[8][H];
    __shared__ float s_WgT[H * GDIM];
    __shared__ float s_pooled[H];

    const int tid  = threadIdx.x;
    const int w    = tid >> 5;
    const int lane = tid & 31;
    const int lh   = lane & 15;      // lane within half
    const int hb   = lane & 16;      // half base (0 or 16)
    const int half = hb >> 4;        // 0 or 1
    const int g    = blockIdx.x;
    const int base = g * NATOMS;
    const unsigned FULL = 0xffffffffu;

    // stage initial embeddings + Wg
    for (int i = tid; i < NATOMS * H; i += 256) s_emb[i] = emb_table[i];
    for (int i = tid; i < GDIM * H; i += 256) {
        int j = i >> 5, k = i & 31;
        s_WgT[k * GDIM + j] = Wg[i];
    }

    float2 pool = make_float2(0.f, 0.f);

    for (int l = 0; l < NCONV; l++) {
        // ---- weights (transposed) ----
        for (int i = tid; i < H * H; i += 256) {
            int k = i >> 5, m = i & 31;
            s_WiT [m * H + k] = W_init[l * H * H + i];
            s_Wo1T[m * H + k] = Wo1[l * H * H + i];
            s_Wo2T[m * H + k] = Wo2[l * H * H + i];
        }
        if (tid < H) {
            s_bo1[tid]  = bo1[l * H + tid];
            s_bo2[tid]  = bo2[l * H + tid];
            s_coef[tid] = coef[l * H + tid];
        }
        __syncthreads();

        // ---- Phase A: h = emb @ Wi^T, 2 atoms per warp per pass ----
        for (int i = 0; i < 7; i++) {
            int a  = i * 16 + 2 * w + half;
            int ae = (a < NATOMS) ? a : 0;
            const float* er = s_emb + ae * H;
            float hx = 0.f, hy = 0.f;
#pragma unroll
            for (int m = 0; m < H; m++) {
                float vm = er[m];
                float2 wv = *(const float2*)&s_WiT[m * H + 2 * lh];
                hx = fmaf(vm, wv.x, hx);
                hy = fmaf(vm, wv.y, hy);
            }
            if (a < NATOMS) *(float2*)&s_h[a * H + 2 * lh] = make_float2(hx, hy);
        }
        __syncthreads();

        // ---- Phase B+C: conv + MLP + residual, 2 nodes per warp ----
        const float4* __restrict__ t4 =
            (const float4*)(g_tblp + (size_t)l * TBL * H);
        const float2 cf = *(const float2*)&s_coef[2 * lh];
        const float2 b1 = *(const float2*)&s_bo1[2 * lh];
        const float2 b2 = *(const float2*)&s_bo2[2 * lh];

        for (int i = 0; i < 7; i++) {
            int a  = i * 16 + 2 * w + half;
            int ae = (a < NATOMS) ? a : 0;
            const uint4* ep = (const uint4*)(g_edges + (size_t)(base + ae) * DEG);

            float nx = 0.f, ny = 0.f, denom = 0.f;
#pragma unroll
            for (int grp = 0; grp < 5; grp++) {
                uint4 pq = __ldg(ep + grp);

                // per-edge msg (2 features per lane)
                float m0x, m0y, m1x, m1y, m2x, m2y, m3x, m3y;
                float q0, q1, q2, q3;
                {
                    unsigned p = pq.x;
                    float2 hd = *(const float2*)&s_h[(p & 127u) * H + 2 * lh];
                    float4 tb = __ldg(&t4[(((p >> 7) & 4095u) << 4) + lh]);
                    float fr = (float)(p >> 19) * (1.0f / 8192.0f);
                    m0x = hd.x * fmaf(fr, tb.y, tb.x);
                    m0y = hd.y * fmaf(fr, tb.w, tb.z);
                    q0 = fmaf(m0x, cf.x, m0y * cf.y);
                }
                {
                    unsigned p = pq.y;
                    float2 hd = *(const float2*)&s_h[(p & 127u) * H + 2 * lh];
                    float4 tb = __ldg(&t4[(((p >> 7) & 4095u) << 4) + lh]);
                    float fr = (float)(p >> 19) * (1.0f / 8192.0f);
                    m1x = hd.x * fmaf(fr, tb.y, tb.x);
                    m1y = hd.y * fmaf(fr, tb.w, tb.z);
                    q1 = fmaf(m1x, cf.x, m1y * cf.y);
                }
                {
                    unsigned p = pq.z;
                    float2 hd = *(const float2*)&s_h[(p & 127u) * H + 2 * lh];
                    float4 tb = __ldg(&t4[(((p >> 7) & 4095u) << 4) + lh]);
                    float fr = (float)(p >> 19) * (1.0f / 8192.0f);
                    m2x = hd.x * fmaf(fr, tb.y, tb.x);
                    m2y = hd.y * fmaf(fr, tb.w, tb.z);
                    q2 = fmaf(m2x, cf.x, m2y * cf.y);
                }
                {
                    unsigned p = pq.w;
                    float2 hd = *(const float2*)&s_h[(p & 127u) * H + 2 * lh];
                    float4 tb = __ldg(&t4[(((p >> 7) & 4095u) << 4) + lh]);
                    float fr = (float)(p >> 19) * (1.0f / 8192.0f);
                    m3x = hd.x * fmaf(fr, tb.y, tb.x);
                    m3y = hd.y * fmaf(fr, tb.w, tb.z);
                    q3 = fmaf(m3x, cf.x, m3y * cf.y);
                }

                // select-merge butterfly: 4 dots over 16 lanes in 5 shfl
                bool b8 = (lane & 8) != 0;
                float z0  = b8 ? q1 : q0;
                float z0x = b8 ? q0 : q1;
                float m01 = z0 + __shfl_xor_sync(FULL, z0x, 8);
                float z1  = b8 ? q3 : q2;
                float z1x = b8 ? q2 : q3;
                float m23 = z1 + __shfl_xor_sync(FULL, z1x, 8);
                bool b4 = (lane & 4) != 0;
                float z2  = b4 ? m23 : m01;
                float z2x = b4 ? m01 : m23;
                float s = z2 + __shfl_xor_sync(FULL, z2x, 4);
                s += __shfl_xor_sync(FULL, s, 2);
                s += __shfl_xor_sync(FULL, s, 1);
                float av = __expf(s);           // one expf per 8 edges
                float a0 = __shfl_sync(FULL, av, hb + 0);
                float a1 = __shfl_sync(FULL, av, hb + 8);
                float a2 = __shfl_sync(FULL, av, hb + 4);
                float a3 = __shfl_sync(FULL, av, hb + 12);

                nx = fmaf(m0x, a0, nx); ny = fmaf(m0y, a0, ny);
                nx = fmaf(m1x, a1, nx); ny = fmaf(m1y, a1, ny);
                nx = fmaf(m2x, a2, nx); ny = fmaf(m2y, a2, ny);
                nx = fmaf(m3x, a3, nx); ny = fmaf(m3y, a3, ny);
                denom += (a0 + a1) + (a2 + a3);
            }

            float cx, cy;
            if (denom > 0.f) {
                float inv = 1.0f / denom;
                cx = nx * inv; cy = ny * inv;
            } else { cx = nx; cy = ny; }

            // MLP: v broadcast via shfl (no smem staging)
            float o1x = b1.x, o1y = b1.y;
#pragma unroll
            for (int m = 0; m < H; m++) {
                float vm = __shfl_sync(FULL, (m & 1) ? cy : cx, hb + (m >> 1));
                float2 wv = *(const float2*)&s_Wo1T[m * H + 2 * lh];
                o1x = fmaf(vm, wv.x, o1x);
                o1y = fmaf(vm, wv.y, o1y);
            }
            o1x = tanh_fast(o1x);
            o1y = tanh_fast(o1y);

            float o2x = b2.x, o2y = b2.y;
#pragma unroll
            for (int m = 0; m < H; m++) {
                float vm = __shfl_sync(FULL, (m & 1) ? o1y : o1x, hb + (m >> 1));
                float2 wv = *(const float2*)&s_Wo2T[m * H + 2 * lh];
                o2x = fmaf(vm, wv.x, o2x);
                o2y = fmaf(vm, wv.y, o2y);
            }

            float2 old = *(const float2*)&s_emb[ae * H + 2 * lh];
            float nex = old.x + o2x;
            float ney = old.y + o2y;
            if (a < NATOMS) {
                if (l < NCONV - 1) {
                    *(float2*)&s_emb[a * H + 2 * lh] = make_float2(nex, ney);
                } else {
                    pool.x += fmaxf(nex, 0.f);
                    pool.y += fmaxf(ney, 0.f);
                }
            }
        }
        __syncthreads();
    }

    // ---- fused pool + final linear ----
    pool.x += __shfl_xor_sync(FULL, pool.x, 16);
    pool.y += __shfl_xor_sync(FULL, pool.y, 16);
    if (lane < 16) {
        s_warp[w][2 * lane]     = pool.x;
        s_warp[w][2 * lane + 1] = pool.y;
    }
    __syncthreads();
    if (w == 0) {
        float p = 0.f;
#pragma unroll
        for (int i = 0; i < 8; i++) p += s_warp[i][lane];
        s_pooled[lane] = p * (1.0f / (float)NATOMS);
        __syncwarp();
        if (lane < GDIM) {
            float o = bg[lane];
#pragma unroll
            for (int k = 0; k < H; k++)
                o = fmaf(s_pooled[k], s_WgT[k * GDIM + lane], o);
            out[g * GDIM + lane] = o;
        }
    }
}

// ============================================================
extern "C" void kernel_launch(void* const* d_in, const int* in_sizes, int n_in,
                              void* d_out, int out_size) {
    const float* data      = (const float*)d_in[0];
    const float* emb_table = (const float*)d_in[1];
    const float* W_init    = (const float*)d_in[2];
    const float* Wf1       = (const float*)d_in[3];
    const float* bf1       = (const float*)d_in[4];
    const float* Wf2       = (const float*)d_in[5];
    const float* bf2       = (const float*)d_in[6];
    const float* coef      = (const float*)d_in[7];
    const float* Wo1       = (const float*)d_in[8];
    const float* bo1       = (const float*)d_in[9];
    const float* Wo2       = (const float*)d_in[10];
    const float* bo2       = (const float*)d_in[11];
    const float* Wg        = (const float*)d_in[12];
    const float* bg        = (const float*)d_in[13];
    float* out = (float*)d_out;

    build_raw_kernel<<<dim3((TBL + 1 + 7) / 8, NCONV), 256>>>(Wf1, bf1, Wf2, bf2);
    pack_edges_kernel<<<(NN * DEG + 255) / 256, 256>>>(data);
    pack_table_kernel<<<(NCONV * TBL * H + 255) / 256, 256>>>();
    fused_kernel<<<NGRAPH, 256>>>(emb_table, W_init, coef,
                                  Wo1, bo1, Wo2, bo2, Wg, bg, out);
}